// round 10
// baseline (speedup 1.0000x reference)
#include <cuda_runtime.h>
#include <cstdint>

#define N_ROWS  2048
#define D_DIM   512
#define H_DIM   512
#define N_HEADS 16

#define TM 64
#define TN 64
#define BK 32
#define KTILES (D_DIM / BK)   // 16
#define ZTILES 4

// padded smem strides (bf16 elements): conflict-free ldmatrix rows
#define ASTRIDE 40   // 80 B
#define WSTRIDE 72   // 144 B

__device__ int g_perm[N_ROWS];
__device__ int g_off[N_HEADS + 1];

// ---------------------------------------------------------------------------
// Kernel 1: counting-sort rows by head (idx int32 or int64, device probe)
// ---------------------------------------------------------------------------
__global__ void bucket_kernel(const int* __restrict__ idxw) {
    __shared__ int cnt[N_HEADS];
    __shared__ int cur[N_HEADS];
    __shared__ int offs[N_HEADS + 1];
    __shared__ int odd_nonzero;
    int tid = threadIdx.x;
    if (tid < N_HEADS) cnt[tid] = 0;
    if (tid == 0) odd_nonzero = 0;
    __syncthreads();
    int local = 0;
    for (int i = tid; i < N_ROWS / 2; i += blockDim.x)
        if (idxw[2 * i + 1] != 0) local = 1;
    if (local) atomicOr(&odd_nonzero, 1);
    __syncthreads();
    const bool is64 = (odd_nonzero == 0);
    for (int i = tid; i < N_ROWS; i += blockDim.x)
        atomicAdd(&cnt[is64 ? idxw[2 * i] : idxw[i]], 1);
    __syncthreads();
    if (tid == 0) {
        int acc = 0;
        for (int h = 0; h < N_HEADS; h++) { offs[h] = acc; cur[h] = acc; acc += cnt[h]; }
        offs[N_HEADS] = acc;
    }
    __syncthreads();
    if (tid <= N_HEADS) g_off[tid] = offs[tid];
    for (int i = tid; i < N_ROWS; i += blockDim.x) {
        int h = is64 ? idxw[2 * i] : idxw[i];
        g_perm[atomicAdd(&cur[h], 1)] = i;
    }
}

// ---------------------------------------------------------------------------
// PTX helpers (baseline ISA only)
// ---------------------------------------------------------------------------
__device__ __forceinline__ uint32_t smem_u32(const void* p) {
    uint32_t a;
    asm("{ .reg .u64 t; cvta.to.shared.u64 t, %1; cvt.u32.u64 %0, t; }"
        : "=r"(a) : "l"(p));
    return a;
}
__device__ __forceinline__ uint32_t bfpack(float lo, float hi) {
    uint32_t r;
    asm("cvt.rn.bf16x2.f32 %0, %1, %2;" : "=r"(r) : "f"(hi), "f"(lo));
    return r;
}
__device__ __forceinline__ void ldsm_x4(uint32_t& r0, uint32_t& r1,
                                        uint32_t& r2, uint32_t& r3, uint32_t a) {
    asm volatile("ldmatrix.sync.aligned.m8n8.x4.shared.b16 {%0,%1,%2,%3}, [%4];"
                 : "=r"(r0), "=r"(r1), "=r"(r2), "=r"(r3) : "r"(a));
}
__device__ __forceinline__ void ldsm_x4t(uint32_t& r0, uint32_t& r1,
                                         uint32_t& r2, uint32_t& r3, uint32_t a) {
    asm volatile("ldmatrix.sync.aligned.m8n8.x4.trans.shared.b16 {%0,%1,%2,%3}, [%4];"
                 : "=r"(r0), "=r"(r1), "=r"(r2), "=r"(r3) : "r"(a));
}
__device__ __forceinline__ void mma16816(float* c, const uint32_t* a,
                                         uint32_t b0, uint32_t b1) {
    asm volatile(
        "mma.sync.aligned.m16n8k16.row.col.f32.bf16.bf16.f32 "
        "{%0,%1,%2,%3}, {%4,%5,%6,%7}, {%8,%9}, {%0,%1,%2,%3};"
        : "+f"(c[0]), "+f"(c[1]), "+f"(c[2]), "+f"(c[3])
        : "r"(a[0]), "r"(a[1]), "r"(a[2]), "r"(a[3]), "r"(b0), "r"(b1));
}
__device__ __forceinline__ void split8(const float* f, uint32_t* hw, uint32_t* lw) {
#pragma unroll
    for (int j = 0; j < 4; j++) {
        float f0 = f[2 * j], f1 = f[2 * j + 1];
        uint32_t h = bfpack(f0, f1);
        float l0 = f0 - __uint_as_float(h << 16);
        float l1 = f1 - __uint_as_float(h & 0xFFFF0000u);
        hw[j] = h;
        lw[j] = bfpack(l0, l1);
    }
}

// ---------------------------------------------------------------------------
// Kernel 2: grouped GEMM via mma.sync bf16 3-split, double-buffered.
// grid = (H/TN, N_HEADS, ZTILES); 256 threads (8 warps, 2m x 4n).
// ---------------------------------------------------------------------------
__global__ __launch_bounds__(256, 2)
void multilinear_mma(const float* __restrict__ X,
                     const float* __restrict__ W,
                     const float* __restrict__ Bb,
                     float* __restrict__ out) {
    const int h    = blockIdx.y;
    const int base = g_off[h];
    const int end  = g_off[h + 1];
    const int n0 = blockIdx.x * TN;

    __shared__ __align__(16) uint16_t Ah[2][TM * ASTRIDE];
    __shared__ __align__(16) uint16_t Al[2][TM * ASTRIDE];
    __shared__ __align__(16) uint16_t Wh[2][BK * WSTRIDE];
    __shared__ __align__(16) uint16_t Wl[2][BK * WSTRIDE];

    const int tid  = threadIdx.x;
    const int wid  = tid >> 5;
    const int lane = tid & 31;

    // conversion-phase mappings
    const int am = tid >> 2;            // m row 0..63
    const int kq = (tid & 3) * 8;       // k chunk
    const int wk = tid >> 3;            // W k row 0..31
    const int wn = (tid & 7) * 8;       // W n chunk
    const float* wbase = W + (size_t)h * D_DIM * H_DIM + (size_t)wk * H_DIM + n0 + wn;

    // mma-phase mappings (warp tile 32x16; 2m x 4n warps)
    const int mw = (wid & 1) * 32;
    const int nw = (wid >> 1) * 16;
    const int a_row = mw + (lane & 7) + 8 * ((lane >> 3) & 1);
    const int a_col = 8 * (lane >> 4);
    const int b_krow = (lane & 7) + 8 * ((lane >> 3) & 1);
    const int b_ncol = nw + 8 * (lane >> 4);

    const float* bp = Bb + (size_t)h * H_DIM;

    for (int row0 = base + blockIdx.z * TM; row0 < end; row0 += ZTILES * TM) {
        const int arowg = row0 + am;
        const int agr   = (arowg < end) ? g_perm[arowg] : g_perm[row0];
        const float* aptr = X + (size_t)agr * D_DIM + kq;

        float acc[2][2][4];
#pragma unroll
        for (int i = 0; i < 2; i++)
#pragma unroll
            for (int j = 0; j < 2; j++)
#pragma unroll
                for (int q = 0; q < 4; q++) acc[i][j][q] = 0.f;

        float4 va[2], vw[2];
        // tile 0 -> regs -> buf0
        va[0] = *reinterpret_cast<const float4*>(aptr);
        va[1] = *reinterpret_cast<const float4*>(aptr + 4);
        vw[0] = *reinterpret_cast<const float4*>(wbase);
        vw[1] = *reinterpret_cast<const float4*>(wbase + 4);
        {
            uint32_t hw[4], lw[4];
            split8(reinterpret_cast<const float*>(va), hw, lw);
            *reinterpret_cast<uint4*>(&Ah[0][am * ASTRIDE + kq]) = make_uint4(hw[0], hw[1], hw[2], hw[3]);
            *reinterpret_cast<uint4*>(&Al[0][am * ASTRIDE + kq]) = make_uint4(lw[0], lw[1], lw[2], lw[3]);
            split8(reinterpret_cast<const float*>(vw), hw, lw);
            *reinterpret_cast<uint4*>(&Wh[0][wk * WSTRIDE + wn]) = make_uint4(hw[0], hw[1], hw[2], hw[3]);
            *reinterpret_cast<uint4*>(&Wl[0][wk * WSTRIDE + wn]) = make_uint4(lw[0], lw[1], lw[2], lw[3]);
        }
        // tile 1 -> regs
        va[0] = *reinterpret_cast<const float4*>(aptr + BK);
        va[1] = *reinterpret_cast<const float4*>(aptr + BK + 4);
        vw[0] = *reinterpret_cast<const float4*>(wbase + (size_t)BK * H_DIM);
        vw[1] = *reinterpret_cast<const float4*>(wbase + (size_t)BK * H_DIM + 4);
        __syncthreads();

        for (int t = 0; t < KTILES; t++) {
            const int cur = t & 1;
            const int nxt = cur ^ 1;

            // convert tile t+1 into nxt buffer (overlaps mma below in issue window)
            if (t + 1 < KTILES) {
                uint32_t hw[4], lw[4];
                split8(reinterpret_cast<const float*>(va), hw, lw);
                *reinterpret_cast<uint4*>(&Ah[nxt][am * ASTRIDE + kq]) = make_uint4(hw[0], hw[1], hw[2], hw[3]);
                *reinterpret_cast<uint4*>(&Al[nxt][am * ASTRIDE + kq]) = make_uint4(lw[0], lw[1], lw[2], lw[3]);
                split8(reinterpret_cast<const float*>(vw), hw, lw);
                *reinterpret_cast<uint4*>(&Wh[nxt][wk * WSTRIDE + wn]) = make_uint4(hw[0], hw[1], hw[2], hw[3]);
                *reinterpret_cast<uint4*>(&Wl[nxt][wk * WSTRIDE + wn]) = make_uint4(lw[0], lw[1], lw[2], lw[3]);
            }
            // prefetch tile t+2 into regs
            if (t + 2 < KTILES) {
                const float* ap = aptr + (t + 2) * BK;
                const float* wp = wbase + (size_t)(t + 2) * BK * H_DIM;
                va[0] = *reinterpret_cast<const float4*>(ap);
                va[1] = *reinterpret_cast<const float4*>(ap + 4);
                vw[0] = *reinterpret_cast<const float4*>(wp);
                vw[1] = *reinterpret_cast<const float4*>(wp + 4);
            }

            // mma on cur buffer
            const uint32_t sAh = smem_u32(Ah[cur]), sAl = smem_u32(Al[cur]);
            const uint32_t sWh = smem_u32(Wh[cur]), sWl = smem_u32(Wl[cur]);
#pragma unroll
            for (int ks = 0; ks < 2; ks++) {
                const int k0 = ks * 16;
                uint32_t ah[2][4], al[2][4], wh[4], wl[4];
#pragma unroll
                for (int mi = 0; mi < 2; mi++) {
                    uint32_t aoff = (uint32_t)(((a_row + mi * 16) * ASTRIDE + k0 + a_col) * 2);
                    ldsm_x4(ah[mi][0], ah[mi][1], ah[mi][2], ah[mi][3], sAh + aoff);
                    ldsm_x4(al[mi][0], al[mi][1], al[mi][2], al[mi][3], sAl + aoff);
                }
                {
                    uint32_t boff = (uint32_t)(((k0 + b_krow) * WSTRIDE + b_ncol) * 2);
                    ldsm_x4t(wh[0], wh[1], wh[2], wh[3], sWh + boff);
                    ldsm_x4t(wl[0], wl[1], wl[2], wl[3], sWl + boff);
                }
                // split-outer order: 4 independent MMAs between acc reuses
#pragma unroll
                for (int mi = 0; mi < 2; mi++)
#pragma unroll
                    for (int ni = 0; ni < 2; ni++)
                        mma16816(acc[mi][ni], ah[mi], wh[2 * ni], wh[2 * ni + 1]);
#pragma unroll
                for (int mi = 0; mi < 2; mi++)
#pragma unroll
                    for (int ni = 0; ni < 2; ni++)
                        mma16816(acc[mi][ni], ah[mi], wl[2 * ni], wl[2 * ni + 1]);
#pragma unroll
                for (int mi = 0; mi < 2; mi++)
#pragma unroll
                    for (int ni = 0; ni < 2; ni++)
                        mma16816(acc[mi][ni], al[mi], wh[2 * ni], wh[2 * ni + 1]);
            }
            __syncthreads();
        }

        // epilogue: bias + scatter to original rows (no smem use)
#pragma unroll
        for (int mi = 0; mi < 2; mi++) {
#pragma unroll
            for (int half = 0; half < 2; half++) {
                const int rloc = mw + mi * 16 + (lane >> 2) + 8 * half;
                const int r    = row0 + rloc;
                if (r < end) {
                    const int orow = g_perm[r];
                    float* op = out + (size_t)orow * H_DIM;
#pragma unroll
                    for (int ni = 0; ni < 2; ni++) {
                        const int c = n0 + nw + ni * 8 + 2 * (lane & 3);
                        float2 v;
                        v.x = acc[mi][ni][2 * half + 0] + bp[c];
                        v.y = acc[mi][ni][2 * half + 1] + bp[c + 1];
                        *reinterpret_cast<float2*>(op + c) = v;
                    }
                }
            }
        }
        __syncthreads();   // protect smem before next m-tile's prologue writes
    }
}

// ---------------------------------------------------------------------------
extern "C" void kernel_launch(void* const* d_in, const int* in_sizes, int n_in,
                              void* d_out, int out_size) {
    const float* X = nullptr; const int* idx = nullptr;
    const float* W = nullptr; const float* B = nullptr;
    for (int i = 0; i < n_in; i++) {
        switch (in_sizes[i]) {
            case 1048576: X   = (const float*)d_in[i]; break;
            case 2048:    idx = (const int*)d_in[i];   break;
            case 4194304: W   = (const float*)d_in[i]; break;
            case 8192:    B   = (const float*)d_in[i]; break;
        }
    }
    float* out = (float*)d_out;

    bucket_kernel<<<1, 256>>>(idx);

    dim3 grid(H_DIM / TN, N_HEADS, ZTILES);
    multilinear_mma<<<grid, 256>>>(X, W, B, out);
}

// round 13
// speedup vs baseline: 1.0894x; 1.0894x over previous
#include <cuda_runtime.h>
#include <cstdint>

#define N_ROWS  2048
#define D_DIM   512
#define H_DIM   512
#define N_HEADS 16

#define TM 64
#define TN 64
#define BK 32
#define KTILES (D_DIM / BK)   // 16
#define ZTILES 8

// padded smem strides (bf16 elements): conflict-free ldmatrix rows
#define ASTRIDE 40   // 80 B rows
#define WSTRIDE 72   // 144 B rows

#define X_ELEMS (N_ROWS * D_DIM)            // 1048576
#define W_ELEMS (N_HEADS * D_DIM * H_DIM)   // 4194304

__device__ int g_perm[N_ROWS];
__device__ int g_off[N_HEADS + 1];
__device__ __align__(16) uint16_t g_Xh[X_ELEMS];   // 2 MB
__device__ __align__(16) uint16_t g_Xl[X_ELEMS];   // 2 MB
__device__ __align__(16) uint16_t g_Wh[W_ELEMS];   // 8 MB
__device__ __align__(16) uint16_t g_Wl[W_ELEMS];   // 8 MB

// ---------------------------------------------------------------------------
// helpers
// ---------------------------------------------------------------------------
__device__ __forceinline__ uint32_t smem_u32(const void* p) {
    uint32_t a;
    asm("{ .reg .u64 t; cvta.to.shared.u64 t, %1; cvt.u32.u64 %0, t; }"
        : "=r"(a) : "l"(p));
    return a;
}
// pack (lo,hi) -> bf16x2 word, lo in low 16 bits
__device__ __forceinline__ uint32_t bfpack(float lo, float hi) {
    uint32_t r;
    asm("cvt.rn.bf16x2.f32 %0, %1, %2;" : "=r"(r) : "f"(hi), "f"(lo));
    return r;
}
__device__ __forceinline__ void ldsm_x4(uint32_t& r0, uint32_t& r1,
                                        uint32_t& r2, uint32_t& r3, uint32_t a) {
    asm volatile("ldmatrix.sync.aligned.m8n8.x4.shared.b16 {%0,%1,%2,%3}, [%4];"
                 : "=r"(r0), "=r"(r1), "=r"(r2), "=r"(r3) : "r"(a));
}
__device__ __forceinline__ void ldsm_x4t(uint32_t& r0, uint32_t& r1,
                                         uint32_t& r2, uint32_t& r3, uint32_t a) {
    asm volatile("ldmatrix.sync.aligned.m8n8.x4.trans.shared.b16 {%0,%1,%2,%3}, [%4];"
                 : "=r"(r0), "=r"(r1), "=r"(r2), "=r"(r3) : "r"(a));
}
__device__ __forceinline__ void mma16816(float* c, const uint32_t* a,
                                         uint32_t b0, uint32_t b1) {
    asm volatile(
        "mma.sync.aligned.m16n8k16.row.col.f32.bf16.bf16.f32 "
        "{%0,%1,%2,%3}, {%4,%5,%6,%7}, {%8,%9}, {%0,%1,%2,%3};"
        : "+f"(c[0]), "+f"(c[1]), "+f"(c[2]), "+f"(c[3])
        : "r"(a[0]), "r"(a[1]), "r"(a[2]), "r"(a[3]), "r"(b0), "r"(b1));
}
__device__ __forceinline__ void cp16(uint32_t saddr, const void* g) {
    asm volatile("cp.async.ca.shared.global [%0], [%1], 16;"
                 :: "r"(saddr), "l"(g));
}
#define CP_COMMIT() asm volatile("cp.async.commit_group;")
#define CP_WAIT(n)  asm volatile("cp.async.wait_group %0;" :: "n"(n))

// ---------------------------------------------------------------------------
// Kernel 1 (prep): block 0 buckets rows by head; all blocks split X and W
// into bf16 hi/lo device scratch.
// ---------------------------------------------------------------------------
__global__ void prep_kernel(const float* __restrict__ X,
                            const float* __restrict__ W,
                            const int* __restrict__ idxw) {
    const int tid = threadIdx.x;

    if (blockIdx.x == 0) {
        __shared__ int cnt[N_HEADS];
        __shared__ int cur[N_HEADS];
        __shared__ int offs[N_HEADS + 1];
        __shared__ int odd_nonzero;
        if (tid < N_HEADS) cnt[tid] = 0;
        if (tid == 0) odd_nonzero = 0;
        __syncthreads();
        int local = 0;
        for (int i = tid; i < N_ROWS / 2; i += blockDim.x)
            if (idxw[2 * i + 1] != 0) local = 1;
        if (local) atomicOr(&odd_nonzero, 1);
        __syncthreads();
        const bool is64 = (odd_nonzero == 0);
        for (int i = tid; i < N_ROWS; i += blockDim.x)
            atomicAdd(&cnt[is64 ? idxw[2 * i] : idxw[i]], 1);
        __syncthreads();
        if (tid == 0) {
            int acc = 0;
            for (int h = 0; h < N_HEADS; h++) { offs[h] = acc; cur[h] = acc; acc += cnt[h]; }
            offs[N_HEADS] = acc;
        }
        __syncthreads();
        if (tid <= N_HEADS) g_off[tid] = offs[tid];
        for (int i = tid; i < N_ROWS; i += blockDim.x) {
            int h = is64 ? idxw[2 * i] : idxw[i];
            g_perm[atomicAdd(&cur[h], 1)] = i;
        }
    }

    // split: grid-stride over float4 elements of X then W
    const int nx4 = X_ELEMS / 4;
    const int total4 = nx4 + W_ELEMS / 4;
    for (int i = blockIdx.x * blockDim.x + tid; i < total4;
         i += gridDim.x * blockDim.x) {
        float4 v;
        if (i < nx4) v = reinterpret_cast<const float4*>(X)[i];
        else         v = reinterpret_cast<const float4*>(W)[i - nx4];

        uint32_t h01 = bfpack(v.x, v.y);
        uint32_t h23 = bfpack(v.z, v.w);
        float lx = v.x - __uint_as_float(h01 << 16);
        float ly = v.y - __uint_as_float(h01 & 0xFFFF0000u);
        float lz = v.z - __uint_as_float(h23 << 16);
        float lw = v.w - __uint_as_float(h23 & 0xFFFF0000u);
        uint32_t l01 = bfpack(lx, ly);
        uint32_t l23 = bfpack(lz, lw);

        if (i < nx4) {
            reinterpret_cast<uint2*>(g_Xh)[i] = make_uint2(h01, h23);
            reinterpret_cast<uint2*>(g_Xl)[i] = make_uint2(l01, l23);
        } else {
            const int j = i - nx4;
            reinterpret_cast<uint2*>(g_Wh)[j] = make_uint2(h01, h23);
            reinterpret_cast<uint2*>(g_Wl)[j] = make_uint2(l01, l23);
        }
    }
}

// ---------------------------------------------------------------------------
// Kernel 2: grouped bf16 3-split GEMM on pre-split operands.
// grid = (H/TN, N_HEADS, ZTILES); 256 threads (8 warps, 2m x 4n), cp.async
// double-buffered, 4 CTAs/SM.
// ---------------------------------------------------------------------------
__global__ __launch_bounds__(256, 4)
void multilinear_mma(const float* __restrict__ Bb, float* __restrict__ out) {
    const int h    = blockIdx.y;
    const int base = g_off[h];
    const int end  = g_off[h + 1];
    const int n0   = blockIdx.x * TN;

    __shared__ __align__(16) uint16_t Ah[2][TM * ASTRIDE];   // 2 x 5 KB
    __shared__ __align__(16) uint16_t Al[2][TM * ASTRIDE];
    __shared__ __align__(16) uint16_t Wh[2][BK * WSTRIDE];   // 2 x 4.5 KB
    __shared__ __align__(16) uint16_t Wl[2][BK * WSTRIDE];

    const int tid  = threadIdx.x;
    const int wid  = tid >> 5;
    const int lane = tid & 31;

    // copy-phase mappings
    const int am = tid >> 2;            // A row 0..63
    const int kq = (tid & 3) * 8;       // A k chunk (8 bf16 = 16B)
    const int wk = tid >> 3;            // W k row 0..31
    const int wn = (tid & 7) * 8;       // W n chunk (8 bf16 = 16B)
    const size_t wgbase = (size_t)h * D_DIM * H_DIM + (size_t)wk * H_DIM + n0 + wn;

    // smem byte addresses (buf0); buf1 = +delta
    const uint32_t sAh0 = smem_u32(&Ah[0][am * ASTRIDE + kq]);
    const uint32_t sAl0 = smem_u32(&Al[0][am * ASTRIDE + kq]);
    const uint32_t sWh0 = smem_u32(&Wh[0][wk * WSTRIDE + wn]);
    const uint32_t sWl0 = smem_u32(&Wl[0][wk * WSTRIDE + wn]);
    const uint32_t dA = TM * ASTRIDE * 2;   // bytes per A buffer
    const uint32_t dW = BK * WSTRIDE * 2;

    // mma-phase mappings (warp tile 32x16; 2m x 4n warps)
    const int mw = (wid & 1) * 32;
    const int nw = (wid >> 1) * 16;
    const int a_row = mw + (lane & 7) + 8 * ((lane >> 3) & 1);
    const int a_col = 8 * (lane >> 4);
    const int b_krow = (lane & 7) + 8 * ((lane >> 3) & 1);
    const int b_ncol = nw + 8 * (lane >> 4);

    const float* bp = Bb + (size_t)h * H_DIM;

    for (int row0 = base + blockIdx.z * TM; row0 < end; row0 += ZTILES * TM) {
        const int arowg = row0 + am;
        const int agr   = (arowg < end) ? g_perm[arowg] : g_perm[row0];
        const size_t agbase = (size_t)agr * D_DIM + kq;

        float acc[2][2][4];
#pragma unroll
        for (int i = 0; i < 2; i++)
#pragma unroll
            for (int j = 0; j < 2; j++)
#pragma unroll
                for (int q = 0; q < 4; q++) acc[i][j][q] = 0.f;

        // prologue: cp tile 0 into buf 0
        cp16(sAh0, g_Xh + agbase);
        cp16(sAl0, g_Xl + agbase);
        cp16(sWh0, g_Wh + wgbase);
        cp16(sWl0, g_Wl + wgbase);
        CP_COMMIT();

#pragma unroll 1
        for (int t = 0; t < KTILES; t++) {
            const int cur = t & 1;

            if (t + 1 < KTILES) {
                const uint32_t bo = (t + 1) & 1;
                const size_t ga = agbase + (size_t)(t + 1) * BK;
                const size_t gw = wgbase + (size_t)(t + 1) * BK * H_DIM;
                cp16(sAh0 + bo * dA, g_Xh + ga);
                cp16(sAl0 + bo * dA, g_Xl + ga);
                cp16(sWh0 + bo * dW, g_Wh + gw);
                cp16(sWl0 + bo * dW, g_Wl + gw);
                CP_COMMIT();
                CP_WAIT(1);
            } else {
                CP_WAIT(0);
            }
            __syncthreads();

            const uint32_t sAhb = smem_u32(Ah[cur]);
            const uint32_t sAlb = smem_u32(Al[cur]);
            const uint32_t sWhb = smem_u32(Wh[cur]);
            const uint32_t sWlb = smem_u32(Wl[cur]);
#pragma unroll
            for (int ks = 0; ks < 2; ks++) {
                const int k0 = ks * 16;
                uint32_t ah[2][4], al[2][4], wh[4], wl[4];
#pragma unroll
                for (int mi = 0; mi < 2; mi++) {
                    uint32_t aoff = (uint32_t)(((a_row + mi * 16) * ASTRIDE + k0 + a_col) * 2);
                    ldsm_x4(ah[mi][0], ah[mi][1], ah[mi][2], ah[mi][3], sAhb + aoff);
                    ldsm_x4(al[mi][0], al[mi][1], al[mi][2], al[mi][3], sAlb + aoff);
                }
                {
                    uint32_t boff = (uint32_t)(((k0 + b_krow) * WSTRIDE + b_ncol) * 2);
                    ldsm_x4t(wh[0], wh[1], wh[2], wh[3], sWhb + boff);
                    ldsm_x4t(wl[0], wl[1], wl[2], wl[3], sWlb + boff);
                }
                // split-outer: independent MMAs between acc reuses
#pragma unroll
                for (int mi = 0; mi < 2; mi++)
#pragma unroll
                    for (int ni = 0; ni < 2; ni++)
                        mma16816(acc[mi][ni], ah[mi], wh[2 * ni], wh[2 * ni + 1]);
#pragma unroll
                for (int mi = 0; mi < 2; mi++)
#pragma unroll
                    for (int ni = 0; ni < 2; ni++)
                        mma16816(acc[mi][ni], ah[mi], wl[2 * ni], wl[2 * ni + 1]);
#pragma unroll
                for (int mi = 0; mi < 2; mi++)
#pragma unroll
                    for (int ni = 0; ni < 2; ni++)
                        mma16816(acc[mi][ni], al[mi], wh[2 * ni], wh[2 * ni + 1]);
            }
            __syncthreads();
        }

        // epilogue: bias + scatter to original rows
#pragma unroll
        for (int mi = 0; mi < 2; mi++) {
#pragma unroll
            for (int half = 0; half < 2; half++) {
                const int rloc = mw + mi * 16 + (lane >> 2) + 8 * half;
                const int r    = row0 + rloc;
                if (r < end) {
                    const int orow = g_perm[r];
                    float* op = out + (size_t)orow * H_DIM;
#pragma unroll
                    for (int ni = 0; ni < 2; ni++) {
                        const int c = n0 + nw + ni * 8 + 2 * (lane & 3);
                        float2 v;
                        v.x = acc[mi][ni][2 * half + 0] + bp[c];
                        v.y = acc[mi][ni][2 * half + 1] + bp[c + 1];
                        *reinterpret_cast<float2*>(op + c) = v;
                    }
                }
            }
        }
    }
}

// ---------------------------------------------------------------------------
extern "C" void kernel_launch(void* const* d_in, const int* in_sizes, int n_in,
                              void* d_out, int out_size) {
    const float* X = nullptr; const int* idx = nullptr;
    const float* W = nullptr; const float* B = nullptr;
    for (int i = 0; i < n_in; i++) {
        switch (in_sizes[i]) {
            case 1048576: X   = (const float*)d_in[i]; break;
            case 2048:    idx = (const int*)d_in[i];   break;
            case 4194304: W   = (const float*)d_in[i]; break;
            case 8192:    B   = (const float*)d_in[i]; break;
        }
    }
    float* out = (float*)d_out;

    prep_kernel<<<2048, 256>>>(X, W, idx);

    dim3 grid(H_DIM / TN, N_HEADS, ZTILES);
    multilinear_mma<<<grid, 256>>>(B, out);
}